// round 13
// baseline (speedup 1.0000x reference)
#include <cuda_runtime.h>
#include <cuda_bf16.h>
#include <cstdint>
#include <math.h>

// ---------------- problem constants ----------------
#define BSZ     2
#define LEN     1024
#define DMODEL  1024
#define DIN     2048      // d_inner
#define NST     16        // n_state
#define DTR     64        // dt_rank
#define XPW     96        // dt_rank + 2*n_state
#define CHUNK   256
#define NC      (LEN / CHUNK)
#define MROWS   (BSZ * LEN)   // 2048
#define XSPLIT  16            // split-K for x_proj

typedef __nv_bfloat16 bf16;

// ---------------- scratch (device globals; no allocation allowed) ----------------
__device__ __align__(16) float g_xr [(size_t)MROWS * 2 * DIN];        // in_proj out (xc|res) fp32
__device__ __align__(16) float g_xp [(size_t)MROWS * XPW];            // x_proj out (dlt|B|C)
__device__ __align__(16) float g_xpp[(size_t)XSPLIT * MROWS * XPW];   // x_proj split-K partials
__device__ __align__(16) uint32_t g_dlp[(size_t)MROWS * DIN];         // delta packed bf16 (h|l<<16)

__device__ __align__(16) bf16 g_xh [(size_t)MROWS * DMODEL];
__device__ __align__(16) bf16 g_xl [(size_t)MROWS * DMODEL];
__device__ __align__(16) bf16 g_uh [(size_t)MROWS * DIN];
__device__ __align__(16) bf16 g_ul [(size_t)MROWS * DIN];
__device__ __align__(16) bf16 g_xph[(size_t)MROWS * DTR];
__device__ __align__(16) bf16 g_xpl[(size_t)MROWS * DTR];
__device__ __align__(16) bf16 g_yh [(size_t)MROWS * DIN];
__device__ __align__(16) bf16 g_yl [(size_t)MROWS * DIN];
__device__ __align__(16) bf16 g_Wih[(size_t)(2 * DIN) * DMODEL];
__device__ __align__(16) bf16 g_Wil[(size_t)(2 * DIN) * DMODEL];
__device__ __align__(16) bf16 g_Wxh[(size_t)XPW * DIN];
__device__ __align__(16) bf16 g_Wxl[(size_t)XPW * DIN];
__device__ __align__(16) bf16 g_Wdh[(size_t)DIN * DTR];
__device__ __align__(16) bf16 g_Wdl[(size_t)DIN * DTR];
__device__ __align__(16) bf16 g_Woh[(size_t)DMODEL * DIN];
__device__ __align__(16) bf16 g_Wol[(size_t)DMODEL * DIN];

// ======================= PTX helpers (sm_80+ subset; valid on plain sm_103) ==============
__device__ __forceinline__ uint32_t smem_u32(const void* p) {
    uint32_t a;
    asm("{ .reg .u64 t; cvta.to.shared.u64 t, %1; cvt.u32.u64 %0, t; }" : "=r"(a) : "l"(p));
    return a;
}
__device__ __forceinline__ void ldsm_x4(uint32_t r[4], uint32_t addr) {
    asm volatile("ldmatrix.sync.aligned.m8n8.x4.shared.b16 {%0,%1,%2,%3}, [%4];"
                 : "=r"(r[0]), "=r"(r[1]), "=r"(r[2]), "=r"(r[3]) : "r"(addr));
}
__device__ __forceinline__ void mma_bf16(float c[4], const uint32_t a[4],
                                         uint32_t b0, uint32_t b1) {
    asm volatile("mma.sync.aligned.m16n8k16.row.col.f32.bf16.bf16.f32 "
                 "{%0,%1,%2,%3}, {%4,%5,%6,%7}, {%8,%9}, {%0,%1,%2,%3};"
                 : "+f"(c[0]), "+f"(c[1]), "+f"(c[2]), "+f"(c[3])
                 : "r"(a[0]), "r"(a[1]), "r"(a[2]), "r"(a[3]), "r"(b0), "r"(b1));
}
#define CP16(dst, src) \
    asm volatile("cp.async.cg.shared.global [%0], [%1], 16;" :: "r"(dst), "l"(src) : "memory")
#define CP16Z(dst, src, sz) \
    asm volatile("cp.async.cg.shared.global [%0], [%1], 16, %2;" :: "r"(dst), "l"(src), "r"(sz) : "memory")
#define CP_COMMIT() asm volatile("cp.async.commit_group;" ::: "memory")
#define CP_WAIT0()  asm volatile("cp.async.wait_group 0;" ::: "memory")
#define CP_WAIT1()  asm volatile("cp.async.wait_group 1;" ::: "memory")

__device__ __forceinline__ void decomp1(float v, bf16& h, bf16& l) {
    h = __float2bfloat16_rn(v);
    l = __float2bfloat16_rn(v - __bfloat162float(h));
}
__device__ __forceinline__ uint32_t pack_hl(float v) {
    bf16 h, l;
    decomp1(v, h, l);
    return (uint32_t)__bfloat16_as_ushort(h) | ((uint32_t)__bfloat16_as_ushort(l) << 16);
}
__device__ __forceinline__ float unpack_hl(uint32_t w) {
    return __bfloat162float(__ushort_as_bfloat16((unsigned short)(w & 0xFFFF))) +
           __bfloat162float(__ushort_as_bfloat16((unsigned short)(w >> 16)));
}

// ========== bf16x3 HMMA GEMM, pre-decomposed bf16 hi/lo inputs, 3-stage cp.async ==========
// C = (Ah+Al)[M,K] @ (Bh+Bl)[N,K]^T ; terms AhBh + AhBl + AlBh, fp32 accumulate.
// Block 128x128, 8 warps (2x4), warp 64x32, K-chunk 32 elems (64B rows).
// Tile rows 64B, XOR swizzle col16 ^= (row>>1)&3  -> conflict-free ldmatrix.
// 3 smem buffers, loads issued 2 chunks ahead, ONE __syncthreads per chunk.
// MODE: 0 = fp32 out (+bias if nonnull), 1 = softplus(+bias) -> packed bf16 hi/lo out.
#define TILEB  (128 * 64)          // 8192
#define OFF_AH 0
#define OFF_AL (1 * TILEB)
#define OFF_BH (2 * TILEB)
#define OFF_BL (3 * TILEB)
#define BUFB   (4 * TILEB)         // 32768
#define GSMEM  (3 * BUFB)          // 98304

template <int MODE>
__global__ void __launch_bounds__(256, 2)
gemm_bf(const bf16* __restrict__ Ah, const bf16* __restrict__ Al,
        const bf16* __restrict__ Bh, const bf16* __restrict__ Bl,
        const float* __restrict__ bias, float* __restrict__ C,
        uint32_t* __restrict__ Cp,
        int M, int N, int K, int lda, int ldb, int ldc)
{
    extern __shared__ __align__(16) char smem[];
    const uint32_t sb = smem_u32(smem);

    const int tid  = threadIdx.x;
    const int lane = tid & 31;
    const int wid  = tid >> 5;
    const int wm   = wid & 1;
    const int wn   = wid >> 1;
    const int brow = blockIdx.y * 128;
    const int bcol = blockIdx.x * 128;

    // split-K slice (no-op when gridDim.z == 1)
    const int koff = blockIdx.z * K;
    Ah += koff; Al += koff; Bh += koff; Bl += koff;
    C += (size_t)blockIdx.z * M * ldc;

    // ---- loader mapping: 2 threads/row; each stores 2x16B per tile ----
    const int lrow  = tid >> 1;
    const int lpart = tid & 1;
    const uint32_t lsw  = ((uint32_t)(lrow >> 1) & 3) << 4;
    const uint32_t d0   = (uint32_t)lrow * 64 + (((uint32_t)lpart * 32) ^ lsw);
    const uint32_t d1   = (uint32_t)lrow * 64 + (((uint32_t)lpart * 32 + 16) ^ lsw);
    const bool bvalid = (bcol + lrow) < N;
    const uint32_t bsz = bvalid ? 16u : 0u;
    const bf16* pAh = Ah + (size_t)(brow + lrow) * lda + lpart * 16;
    const bf16* pAl = Al + (size_t)(brow + lrow) * lda + lpart * 16;
    const bf16* pBh = Bh + (size_t)(bvalid ? (bcol + lrow) : 0) * ldb + lpart * 16;
    const bf16* pBl = Bl + (size_t)(bvalid ? (bcol + lrow) : 0) * ldb + lpart * 16;

    // ---- ldmatrix per-lane bases ----
    const uint32_t arow = (uint32_t)(wm * 64 + (lane & 15));
    const uint32_t acol = ((uint32_t)lane >> 4) * 16;
    const uint32_t asw  = ((arow >> 1) & 3) << 4;
    const uint32_t aroff = arow * 64;
    const uint32_t brl  = (uint32_t)(wn * 32 + (((lane >> 4) & 1) << 3) + (lane & 7));
    const uint32_t bcl  = (((uint32_t)lane >> 3) & 1) * 16;
    const uint32_t bsw  = ((brl >> 1) & 3) << 4;
    const uint32_t broff = brl * 64;

    float c[4][4][4];
#pragma unroll
    for (int mi = 0; mi < 4; mi++)
#pragma unroll
        for (int ni = 0; ni < 4; ni++)
#pragma unroll
            for (int r = 0; r < 4; r++) c[mi][ni][r] = 0.f;

    const int nchunks = K >> 5;

    auto load_chunk = [&](int buf, int k0) {
        const uint32_t bb = sb + (uint32_t)buf * BUFB;
        CP16 (bb + OFF_AH + d0, pAh + k0);
        CP16 (bb + OFF_AH + d1, pAh + k0 + 8);
        CP16 (bb + OFF_AL + d0, pAl + k0);
        CP16 (bb + OFF_AL + d1, pAl + k0 + 8);
        CP16Z(bb + OFF_BH + d0, pBh + k0,     bsz);
        CP16Z(bb + OFF_BH + d1, pBh + k0 + 8, bsz);
        CP16Z(bb + OFF_BL + d0, pBl + k0,     bsz);
        CP16Z(bb + OFF_BL + d1, pBl + k0 + 8, bsz);
        CP_COMMIT();
    };

    load_chunk(0, 0);
    if (nchunks > 1) load_chunk(1, 32);

    int buf = 0;
    for (int ck = 0; ck < nchunks; ck++) {
        if (ck + 1 < nchunks) CP_WAIT1(); else CP_WAIT0();
        __syncthreads();
        if (ck + 2 < nchunks) {
            int nb = buf + 2; if (nb >= 3) nb -= 3;
            load_chunk(nb, (ck + 2) * 32);
        }

        const uint32_t ub = sb + (uint32_t)buf * BUFB;
#pragma unroll
        for (int ks = 0; ks < 2; ks++) {
            const uint32_t ac = (acol + ks * 32) ^ asw;
            const uint32_t bc = (bcl  + ks * 32) ^ bsw;
            uint32_t bh[2][4], bl[2][4];
#pragma unroll
            for (int np = 0; np < 2; np++) {
                const uint32_t o = broff + np * 1024 + bc;
                ldsm_x4(bh[np], ub + OFF_BH + o);
                ldsm_x4(bl[np], ub + OFF_BL + o);
            }
#pragma unroll
            for (int mi = 0; mi < 4; mi++) {
                uint32_t ah[4], al[4];
                const uint32_t o = aroff + mi * 1024 + ac;
                ldsm_x4(ah, ub + OFF_AH + o);
                ldsm_x4(al, ub + OFF_AL + o);
#pragma unroll
                for (int np = 0; np < 2; np++)
#pragma unroll
                    for (int s = 0; s < 2; s++) {
                        const int ni = np * 2 + s;
                        mma_bf16(c[mi][ni], ah, bh[np][s * 2], bh[np][s * 2 + 1]);
                        mma_bf16(c[mi][ni], ah, bl[np][s * 2], bl[np][s * 2 + 1]);
                        mma_bf16(c[mi][ni], al, bh[np][s * 2], bh[np][s * 2 + 1]);
                    }
            }
        }
        if (++buf >= 3) buf -= 3;
    }

    // ---- epilogue ----
#pragma unroll
    for (int mi = 0; mi < 4; mi++) {
        const int r0 = brow + wm * 64 + mi * 16 + (lane >> 2);
#pragma unroll
        for (int ni = 0; ni < 4; ni++) {
            const int col = bcol + wn * 32 + ni * 8 + (lane & 3) * 2;
#pragma unroll
            for (int half = 0; half < 2; half++) {
                const int row = r0 + half * 8;
                float v0 = c[mi][ni][half * 2 + 0];
                float v1 = c[mi][ni][half * 2 + 1];
                if (MODE == 0) {
                    if (col + 1 < N) {
                        if (bias) { v0 += bias[col]; v1 += bias[col + 1]; }
                        *(float2*)(C + (size_t)row * ldc + col) = make_float2(v0, v1);
                    } else if (col < N) {
                        if (bias) v0 += bias[col];
                        C[(size_t)row * ldc + col] = v0;
                    }
                } else {
                    // softplus -> packed bf16 hi/lo (cols in-bounds for this GEMM)
                    v0 += bias[col];
                    v1 += bias[col + 1];
                    v0 = (v0 > 20.f) ? v0 : log1pf(__expf(v0));
                    v1 = (v1 > 20.f) ? v1 : log1pf(__expf(v1));
                    const size_t o = (size_t)row * ldc + col;
                    *(uint2*)(Cp + o) = make_uint2(pack_hl(v0), pack_hl(v1));
                }
            }
        }
    }
}

// ---------------- one-pass fp32 -> bf16 hi/lo decomposition (x + 4 weights) ----------------
#define DN0 (MROWS * DMODEL)
#define DN1 (2 * DIN * DMODEL)
#define DN2 (XPW * DIN)
#define DN3 (DIN * DTR)
#define DN4 (DMODEL * DIN)
#define DNT (DN0 + DN1 + DN2 + DN3 + DN4)

__global__ void __launch_bounds__(256)
decomp_all(const float* __restrict__ x,  const float* __restrict__ Wi,
           const float* __restrict__ Wx, const float* __restrict__ Wd,
           const float* __restrict__ Wo)
{
    int i = (blockIdx.x * 256 + threadIdx.x) * 4;
    if (i >= DNT) return;
    const float* s; bf16 *h, *l;
    if (i < DN0)                          { s = x  + i;                        h = g_xh  + i;  l = g_xl  + i; }
    else if (i < DN0 + DN1)               { int j = i - DN0;                   s = Wi + j; h = g_Wih + j; l = g_Wil + j; }
    else if (i < DN0 + DN1 + DN2)         { int j = i - DN0 - DN1;             s = Wx + j; h = g_Wxh + j; l = g_Wxl + j; }
    else if (i < DN0 + DN1 + DN2 + DN3)   { int j = i - DN0 - DN1 - DN2;       s = Wd + j; h = g_Wdh + j; l = g_Wdl + j; }
    else                                  { int j = i - DN0 - DN1 - DN2 - DN3; s = Wo + j; h = g_Woh + j; l = g_Wol + j; }
    float4 v = *(const float4*)s;
    bf16 h0, l0, h1, l1, h2, l2, h3, l3;
    decomp1(v.x, h0, l0); decomp1(v.y, h1, l1);
    decomp1(v.z, h2, l2); decomp1(v.w, h3, l3);
    *(uint2*)h = make_uint2(
        (uint32_t)__bfloat16_as_ushort(h0) | ((uint32_t)__bfloat16_as_ushort(h1) << 16),
        (uint32_t)__bfloat16_as_ushort(h2) | ((uint32_t)__bfloat16_as_ushort(h3) << 16));
    *(uint2*)l = make_uint2(
        (uint32_t)__bfloat16_as_ushort(l0) | ((uint32_t)__bfloat16_as_ushort(l1) << 16),
        (uint32_t)__bfloat16_as_ushort(l2) | ((uint32_t)__bfloat16_as_ushort(l3) << 16));
}

// ---------------- split-K reduce for x_proj (+ hi/lo of delta-lowrank cols) ----------------
__global__ void reduce_xp_kernel(const float* __restrict__ part, float* __restrict__ xp,
                                 bf16* __restrict__ xph, bf16* __restrict__ xpl)
{
    const int i = blockIdx.x * 256 + threadIdx.x;
    if (i >= MROWS * XPW) return;
    float s = 0.f;
#pragma unroll
    for (int k = 0; k < XSPLIT; k++) s += part[(size_t)k * MROWS * XPW + i];
    xp[i] = s;
    const int col = i % XPW;
    if (col < DTR) {
        const int row = i / XPW;
        bf16 h, l;
        decomp1(s, h, l);
        xph[row * DTR + col] = h;
        xpl[row * DTR + col] = l;
    }
}

// ---------------- depthwise causal conv1d (k=3) + SiLU -> bf16 hi/lo ----------------
__global__ void conv_silu_kernel(const float* __restrict__ xr,
                                 const float* __restrict__ conv_w,
                                 const float* __restrict__ conv_b,
                                 bf16* __restrict__ uh, bf16* __restrict__ ul)
{
    const int idx = blockIdx.x * blockDim.x + threadIdx.x;
    if (idx >= MROWS * DIN) return;
    const int d = idx % DIN;
    const int l = (idx / DIN) % LEN;
    const int b = idx / (DIN * LEN);

    const float* xc = xr + (size_t)b * LEN * (2 * DIN);
    const float w0 = conv_w[d * 3 + 0];
    const float w1 = conv_w[d * 3 + 1];
    const float w2 = conv_w[d * 3 + 2];

    float acc = conv_b[d];
    if (l >= 2) acc = fmaf(w0, xc[(size_t)(l - 2) * (2 * DIN) + d], acc);
    if (l >= 1) acc = fmaf(w1, xc[(size_t)(l - 1) * (2 * DIN) + d], acc);
    acc = fmaf(w2, xc[(size_t)l * (2 * DIN) + d], acc);
    const float v = acc / (1.f + __expf(-acc));
    bf16 h, lo;
    decomp1(v, h, lo);
    uh[idx] = h;
    ul[idx] = lo;
}

// ---------------- chunked selective scan + output gate -> bf16 hi/lo ----------------
// grid (DIN/128, NC, BSZ), block 128 -> 128 CTAs for better SM coverage.
__global__ void __launch_bounds__(128)
scan_kernel(const float* __restrict__ xp,
            const uint32_t* __restrict__ dlp,
            const bf16* __restrict__ uh,  const bf16* __restrict__ ul,
            const float* __restrict__ xr, const float* __restrict__ A_log,
            bf16* __restrict__ yh, bf16* __restrict__ yl)
{
    const int d = blockIdx.x * 128 + threadIdx.x;
    const int c = blockIdx.y;
    const int b = blockIdx.z;
    const int base_l = c * CHUNK;

    __shared__ float Bs[CHUNK][NST];
    __shared__ float Cs[CHUNK][NST];
    for (int i = threadIdx.x; i < CHUNK * NST; i += 128) {
        const int l = i / NST, n = i % NST;
        const float* row = xp + (size_t)(b * LEN + base_l + l) * XPW;
        Bs[l][n] = row[DTR + n];
        Cs[l][n] = row[DTR + NST + n];
    }
    __syncthreads();

    float aA[NST];
#pragma unroll
    for (int n = 0; n < NST; n++) aA[n] = -__expf(A_log[d * NST + n]);

    float s[NST];
#pragma unroll
    for (int n = 0; n < NST; n++) s[n] = 0.f;

    for (int l = 0; l < CHUNK; l++) {
        const size_t idx = (size_t)(b * LEN + base_l + l) * DIN + d;
        const float dl = unpack_hl(dlp[idx]);
        const float uu = __bfloat162float(uh[idx]) + __bfloat162float(ul[idx]);
        const float du = dl * uu;
        float acc = 0.f;
#pragma unroll
        for (int n = 0; n < NST; n++) {
            const float dA = __expf(dl * aA[n]);
            s[n] = fmaf(dA, s[n], du * Bs[l][n]);
            acc  = fmaf(s[n], Cs[l][n], acc);
        }
        const float r  = xr[(size_t)(b * LEN + base_l + l) * (2 * DIN) + DIN + d];
        const float sr = r / (1.f + __expf(-r));
        const float yv = acc * sr;
        bf16 h, lo;
        decomp1(yv, h, lo);
        yh[idx] = h;
        yl[idx] = lo;
    }
}

// ---------------- launcher ----------------
extern "C" void kernel_launch(void* const* d_in, const int* in_sizes, int n_in,
                              void* d_out, int out_size)
{
    const float* x      = (const float*)d_in[0];
    const float* W_in   = (const float*)d_in[1];
    const float* b_in   = (const float*)d_in[2];
    const float* conv_w = (const float*)d_in[3];
    const float* conv_b = (const float*)d_in[4];
    const float* W_x    = (const float*)d_in[5];
    const float* W_dt   = (const float*)d_in[6];
    const float* b_dt   = (const float*)d_in[7];
    const float* A_log  = (const float*)d_in[8];
    const float* W_out  = (const float*)d_in[9];
    const float* b_out  = (const float*)d_in[10];
    float* out = (float*)d_out;

    float *xr, *xp, *xpp;
    uint32_t* dlp;
    bf16 *xh, *xl, *uh, *ul, *xph, *xpl, *yh, *yl;
    bf16 *Wih, *Wil, *Wxh, *Wxl, *Wdh, *Wdl, *Woh, *Wol;
    cudaGetSymbolAddress((void**)&xr,  g_xr);
    cudaGetSymbolAddress((void**)&xp,  g_xp);
    cudaGetSymbolAddress((void**)&xpp, g_xpp);
    cudaGetSymbolAddress((void**)&dlp, g_dlp);
    cudaGetSymbolAddress((void**)&xh,  g_xh);
    cudaGetSymbolAddress((void**)&xl,  g_xl);
    cudaGetSymbolAddress((void**)&uh,  g_uh);
    cudaGetSymbolAddress((void**)&ul,  g_ul);
    cudaGetSymbolAddress((void**)&xph, g_xph);
    cudaGetSymbolAddress((void**)&xpl, g_xpl);
    cudaGetSymbolAddress((void**)&yh,  g_yh);
    cudaGetSymbolAddress((void**)&yl,  g_yl);
    cudaGetSymbolAddress((void**)&Wih, g_Wih);
    cudaGetSymbolAddress((void**)&Wil, g_Wil);
    cudaGetSymbolAddress((void**)&Wxh, g_Wxh);
    cudaGetSymbolAddress((void**)&Wxl, g_Wxl);
    cudaGetSymbolAddress((void**)&Wdh, g_Wdh);
    cudaGetSymbolAddress((void**)&Wdl, g_Wdl);
    cudaGetSymbolAddress((void**)&Woh, g_Woh);
    cudaGetSymbolAddress((void**)&Wol, g_Wol);

    cudaFuncSetAttribute(gemm_bf<0>, cudaFuncAttributeMaxDynamicSharedMemorySize, GSMEM);
    cudaFuncSetAttribute(gemm_bf<1>, cudaFuncAttributeMaxDynamicSharedMemorySize, GSMEM);

    // 0) decompose x + all weights -> bf16 hi/lo
    decomp_all<<<(DNT / 4 + 255) / 256, 256>>>(x, W_in, W_x, W_dt, W_out);

    // 1) in_proj: xr[2048,4096] = x @ W_in^T + b_in  (fp32 out)
    gemm_bf<0><<<dim3(2 * DIN / 128, MROWS / 128, 1), 256, GSMEM>>>(
        xh, xl, Wih, Wil, b_in, xr, nullptr,
        MROWS, 2 * DIN, DMODEL, DMODEL, DMODEL, 2 * DIN);

    // 2) depthwise causal conv + silu -> uh/ul
    conv_silu_kernel<<<(MROWS * DIN + 255) / 256, 256>>>(xr, conv_w, conv_b, uh, ul);

    // 3) x_proj split-K partials (16 slices of K=128)
    gemm_bf<0><<<dim3(1, MROWS / 128, XSPLIT), 256, GSMEM>>>(
        uh, ul, Wxh, Wxl, nullptr, xpp, nullptr,
        MROWS, XPW, DIN / XSPLIT, DIN, DIN, XPW);

    // 3b) reduce partials -> xp (+ hi/lo of dlt cols)
    reduce_xp_kernel<<<(MROWS * XPW + 255) / 256, 256>>>(xpp, xp, xph, xpl);

    // 4) delta = softplus( dlt @ W_dt^T + b_dt ) -> packed bf16 hi/lo
    gemm_bf<1><<<dim3(DIN / 128, MROWS / 128, 1), 256, GSMEM>>>(
        xph, xpl, Wdh, Wdl, b_dt, nullptr, dlp,
        MROWS, DIN, DTR, DTR, DTR, DIN);

    // 5) chunked scan + gate -> yh/yl  (128 CTAs)
    scan_kernel<<<dim3(DIN / 128, NC, BSZ), 128>>>(xp, dlp, uh, ul, xr, A_log, yh, yl);

    // 6) out_proj: out = y @ W_out^T + b_out  (direct, no split-K; 128 CTAs = 1 wave)
    gemm_bf<0><<<dim3(DMODEL / 128, MROWS / 128, 1), 256, GSMEM>>>(
        yh, yl, Woh, Wol, b_out, out, nullptr,
        MROWS, DMODEL, DIN, DIN, DIN, DMODEL);
}

// round 14
// speedup vs baseline: 1.4062x; 1.4062x over previous
#include <cuda_runtime.h>
#include <cuda_bf16.h>
#include <cstdint>
#include <math.h>

// ---------------- problem constants ----------------
#define BSZ     2
#define LEN     1024
#define DMODEL  1024
#define DIN     2048      // d_inner
#define NST     16        // n_state
#define DTR     64        // dt_rank
#define XPW     96        // dt_rank + 2*n_state
#define CHUNK   256
#define NC      (LEN / CHUNK)
#define MROWS   (BSZ * LEN)   // 2048
#define XSPLIT  16            // split-K for x_proj
#define OSPLIT  2             // split-K for out_proj

typedef __nv_bfloat16 bf16;

// ---------------- scratch (device globals; no allocation allowed) ----------------
__device__ __align__(16) float g_xr [(size_t)MROWS * 2 * DIN];        // in_proj out (xc|res) fp32
__device__ __align__(16) float g_xp [(size_t)MROWS * XPW];            // x_proj out (dlt|B|C)
__device__ __align__(16) float g_xpp[(size_t)XSPLIT * MROWS * XPW];   // x_proj split-K partials
__device__ __align__(16) float g_op [(size_t)OSPLIT * MROWS * DMODEL];// out_proj partials

__device__ __align__(16) bf16 g_xh [(size_t)MROWS * DMODEL];
__device__ __align__(16) bf16 g_xl [(size_t)MROWS * DMODEL];
__device__ __align__(16) bf16 g_uh [(size_t)MROWS * DIN];
__device__ __align__(16) bf16 g_ul [(size_t)MROWS * DIN];
__device__ __align__(16) bf16 g_xph[(size_t)MROWS * DTR];
__device__ __align__(16) bf16 g_xpl[(size_t)MROWS * DTR];
__device__ __align__(16) bf16 g_dlh[(size_t)MROWS * DIN];
__device__ __align__(16) bf16 g_dll[(size_t)MROWS * DIN];
__device__ __align__(16) bf16 g_yh [(size_t)MROWS * DIN];
__device__ __align__(16) bf16 g_yl [(size_t)MROWS * DIN];
__device__ __align__(16) bf16 g_Wih[(size_t)(2 * DIN) * DMODEL];
__device__ __align__(16) bf16 g_Wil[(size_t)(2 * DIN) * DMODEL];
__device__ __align__(16) bf16 g_Wxh[(size_t)XPW * DIN];
__device__ __align__(16) bf16 g_Wxl[(size_t)XPW * DIN];
__device__ __align__(16) bf16 g_Wdh[(size_t)DIN * DTR];
__device__ __align__(16) bf16 g_Wdl[(size_t)DIN * DTR];
__device__ __align__(16) bf16 g_Woh[(size_t)DMODEL * DIN];
__device__ __align__(16) bf16 g_Wol[(size_t)DMODEL * DIN];

// ======================= PTX helpers (sm_80+ subset; valid on plain sm_103) ==============
__device__ __forceinline__ uint32_t smem_u32(const void* p) {
    uint32_t a;
    asm("{ .reg .u64 t; cvta.to.shared.u64 t, %1; cvt.u32.u64 %0, t; }" : "=r"(a) : "l"(p));
    return a;
}
__device__ __forceinline__ void ldsm_x4(uint32_t r[4], uint32_t addr) {
    asm volatile("ldmatrix.sync.aligned.m8n8.x4.shared.b16 {%0,%1,%2,%3}, [%4];"
                 : "=r"(r[0]), "=r"(r[1]), "=r"(r[2]), "=r"(r[3]) : "r"(addr));
}
__device__ __forceinline__ void mma_bf16(float c[4], const uint32_t a[4],
                                         uint32_t b0, uint32_t b1) {
    asm volatile("mma.sync.aligned.m16n8k16.row.col.f32.bf16.bf16.f32 "
                 "{%0,%1,%2,%3}, {%4,%5,%6,%7}, {%8,%9}, {%0,%1,%2,%3};"
                 : "+f"(c[0]), "+f"(c[1]), "+f"(c[2]), "+f"(c[3])
                 : "r"(a[0]), "r"(a[1]), "r"(a[2]), "r"(a[3]), "r"(b0), "r"(b1));
}
#define CP16(dst, src) \
    asm volatile("cp.async.cg.shared.global [%0], [%1], 16;" :: "r"(dst), "l"(src) : "memory")
#define CP16Z(dst, src, sz) \
    asm volatile("cp.async.cg.shared.global [%0], [%1], 16, %2;" :: "r"(dst), "l"(src), "r"(sz) : "memory")
#define CP_COMMIT() asm volatile("cp.async.commit_group;" ::: "memory")
#define CP_WAIT0()  asm volatile("cp.async.wait_group 0;" ::: "memory")
#define CP_WAIT1()  asm volatile("cp.async.wait_group 1;" ::: "memory")

__device__ __forceinline__ void decomp1(float v, bf16& h, bf16& l) {
    h = __float2bfloat16_rn(v);
    l = __float2bfloat16_rn(v - __bfloat162float(h));
}

// ========== bf16x3 HMMA GEMM, pre-decomposed bf16 hi/lo inputs, 3-stage cp.async ==========
// C = (Ah+Al)[M,K] @ (Bh+Bl)[N,K]^T ; terms AhBh + AhBl + AlBh, fp32 accumulate.
// Block 128x128, 8 warps (2x4), warp 64x32, K-chunk 32 elems (64B rows).
// Tile rows 64B, XOR swizzle col16 ^= (row>>1)&3  -> conflict-free ldmatrix.
// 3 smem buffers, loads issued 2 chunks ahead, ONE __syncthreads per chunk.
// MMA schedule: mi-pairs, TERM-MAJOR (8-MMA RAW distance per accumulator) to cover
// HMMA latency instead of stalling on back-to-back dependent MMAs.
// MODE: 0 = fp32 out (+bias if nonnull), 1 = softplus(+bias) -> bf16 hi/lo out.
#define TILEB  (128 * 64)          // 8192
#define OFF_AH 0
#define OFF_AL (1 * TILEB)
#define OFF_BH (2 * TILEB)
#define OFF_BL (3 * TILEB)
#define BUFB   (4 * TILEB)         // 32768
#define GSMEM  (3 * BUFB)          // 98304

template <int MODE>
__global__ void __launch_bounds__(256, 2)
gemm_bf(const bf16* __restrict__ Ah, const bf16* __restrict__ Al,
        const bf16* __restrict__ Bh, const bf16* __restrict__ Bl,
        const float* __restrict__ bias, float* __restrict__ C,
        bf16* __restrict__ Ch, bf16* __restrict__ Cl,
        int M, int N, int K, int lda, int ldb, int ldc)
{
    extern __shared__ __align__(16) char smem[];
    const uint32_t sb = smem_u32(smem);

    const int tid  = threadIdx.x;
    const int lane = tid & 31;
    const int wid  = tid >> 5;
    const int wm   = wid & 1;
    const int wn   = wid >> 1;
    const int brow = blockIdx.y * 128;
    const int bcol = blockIdx.x * 128;

    // split-K slice (no-op when gridDim.z == 1)
    const int koff = blockIdx.z * K;
    Ah += koff; Al += koff; Bh += koff; Bl += koff;
    C += (size_t)blockIdx.z * M * ldc;

    // ---- loader mapping: 2 threads/row; each stores 2x16B per tile ----
    const int lrow  = tid >> 1;
    const int lpart = tid & 1;
    const uint32_t lsw  = ((uint32_t)(lrow >> 1) & 3) << 4;
    const uint32_t d0   = (uint32_t)lrow * 64 + (((uint32_t)lpart * 32) ^ lsw);
    const uint32_t d1   = (uint32_t)lrow * 64 + (((uint32_t)lpart * 32 + 16) ^ lsw);
    const bool bvalid = (bcol + lrow) < N;
    const uint32_t bsz = bvalid ? 16u : 0u;
    const bf16* pAh = Ah + (size_t)(brow + lrow) * lda + lpart * 16;
    const bf16* pAl = Al + (size_t)(brow + lrow) * lda + lpart * 16;
    const bf16* pBh = Bh + (size_t)(bvalid ? (bcol + lrow) : 0) * ldb + lpart * 16;
    const bf16* pBl = Bl + (size_t)(bvalid ? (bcol + lrow) : 0) * ldb + lpart * 16;

    // ---- ldmatrix per-lane bases ----
    const uint32_t arow = (uint32_t)(wm * 64 + (lane & 15));
    const uint32_t acol = ((uint32_t)lane >> 4) * 16;
    const uint32_t asw  = ((arow >> 1) & 3) << 4;
    const uint32_t aroff = arow * 64;
    const uint32_t brl  = (uint32_t)(wn * 32 + (((lane >> 4) & 1) << 3) + (lane & 7));
    const uint32_t bcl  = (((uint32_t)lane >> 3) & 1) * 16;
    const uint32_t bsw  = ((brl >> 1) & 3) << 4;
    const uint32_t broff = brl * 64;

    float c[4][4][4];
#pragma unroll
    for (int mi = 0; mi < 4; mi++)
#pragma unroll
        for (int ni = 0; ni < 4; ni++)
#pragma unroll
            for (int r = 0; r < 4; r++) c[mi][ni][r] = 0.f;

    const int nchunks = K >> 5;

    auto load_chunk = [&](int buf, int k0) {
        const uint32_t bb = sb + (uint32_t)buf * BUFB;
        CP16 (bb + OFF_AH + d0, pAh + k0);
        CP16 (bb + OFF_AH + d1, pAh + k0 + 8);
        CP16 (bb + OFF_AL + d0, pAl + k0);
        CP16 (bb + OFF_AL + d1, pAl + k0 + 8);
        CP16Z(bb + OFF_BH + d0, pBh + k0,     bsz);
        CP16Z(bb + OFF_BH + d1, pBh + k0 + 8, bsz);
        CP16Z(bb + OFF_BL + d0, pBl + k0,     bsz);
        CP16Z(bb + OFF_BL + d1, pBl + k0 + 8, bsz);
        CP_COMMIT();
    };

    load_chunk(0, 0);
    if (nchunks > 1) load_chunk(1, 32);

    int buf = 0;
    for (int ck = 0; ck < nchunks; ck++) {
        if (ck + 1 < nchunks) CP_WAIT1(); else CP_WAIT0();
        __syncthreads();
        if (ck + 2 < nchunks) {
            int nb = buf + 2; if (nb >= 3) nb -= 3;
            load_chunk(nb, (ck + 2) * 32);
        }

        const uint32_t ub = sb + (uint32_t)buf * BUFB;
#pragma unroll
        for (int ks = 0; ks < 2; ks++) {
            const uint32_t ac = (acol + ks * 32) ^ asw;
            const uint32_t bc = (bcl  + ks * 32) ^ bsw;
            uint32_t bh[2][4], bl[2][4];
#pragma unroll
            for (int np = 0; np < 2; np++) {
                const uint32_t o = broff + np * 1024 + bc;
                ldsm_x4(bh[np], ub + OFF_BH + o);
                ldsm_x4(bl[np], ub + OFF_BL + o);
            }
            // mi processed in pairs; within a pair the three bf16x3 terms are
            // issued TERM-MAJOR: 8 independent MMAs between dependent updates
            // of the same accumulator -> HMMA latency covered by issue stream.
#pragma unroll
            for (int mp = 0; mp < 2; mp++) {
                uint32_t ah[2][4], al[2][4];
#pragma unroll
                for (int m2 = 0; m2 < 2; m2++) {
                    const uint32_t o = aroff + (mp * 2 + m2) * 1024 + ac;
                    ldsm_x4(ah[m2], ub + OFF_AH + o);
                    ldsm_x4(al[m2], ub + OFF_AL + o);
                }
                // term 1: Ah * Bh
#pragma unroll
                for (int m2 = 0; m2 < 2; m2++)
#pragma unroll
                    for (int np = 0; np < 2; np++)
#pragma unroll
                        for (int s = 0; s < 2; s++)
                            mma_bf16(c[mp * 2 + m2][np * 2 + s], ah[m2],
                                     bh[np][s * 2], bh[np][s * 2 + 1]);
                // term 2: Ah * Bl
#pragma unroll
                for (int m2 = 0; m2 < 2; m2++)
#pragma unroll
                    for (int np = 0; np < 2; np++)
#pragma unroll
                        for (int s = 0; s < 2; s++)
                            mma_bf16(c[mp * 2 + m2][np * 2 + s], ah[m2],
                                     bl[np][s * 2], bl[np][s * 2 + 1]);
                // term 3: Al * Bh
#pragma unroll
                for (int m2 = 0; m2 < 2; m2++)
#pragma unroll
                    for (int np = 0; np < 2; np++)
#pragma unroll
                        for (int s = 0; s < 2; s++)
                            mma_bf16(c[mp * 2 + m2][np * 2 + s], al[m2],
                                     bh[np][s * 2], bh[np][s * 2 + 1]);
            }
        }
        if (++buf >= 3) buf -= 3;
    }

    // ---- epilogue ----
#pragma unroll
    for (int mi = 0; mi < 4; mi++) {
        const int r0 = brow + wm * 64 + mi * 16 + (lane >> 2);
#pragma unroll
        for (int ni = 0; ni < 4; ni++) {
            const int col = bcol + wn * 32 + ni * 8 + (lane & 3) * 2;
#pragma unroll
            for (int half = 0; half < 2; half++) {
                const int row = r0 + half * 8;
                float v0 = c[mi][ni][half * 2 + 0];
                float v1 = c[mi][ni][half * 2 + 1];
                if (MODE == 0) {
                    if (col + 1 < N) {
                        if (bias) { v0 += bias[col]; v1 += bias[col + 1]; }
                        *(float2*)(C + (size_t)row * ldc + col) = make_float2(v0, v1);
                    } else if (col < N) {
                        if (bias) v0 += bias[col];
                        C[(size_t)row * ldc + col] = v0;
                    }
                } else {
                    // softplus -> bf16 hi/lo packed pair (cols in-bounds for this GEMM)
                    v0 += bias[col];
                    v1 += bias[col + 1];
                    v0 = (v0 > 20.f) ? v0 : log1pf(__expf(v0));
                    v1 = (v1 > 20.f) ? v1 : log1pf(__expf(v1));
                    bf16 h0, l0, h1, l1;
                    decomp1(v0, h0, l0);
                    decomp1(v1, h1, l1);
                    const size_t o = (size_t)row * ldc + col;
                    *(uint32_t*)(Ch + o) = (uint32_t)__bfloat16_as_ushort(h0) |
                                           ((uint32_t)__bfloat16_as_ushort(h1) << 16);
                    *(uint32_t*)(Cl + o) = (uint32_t)__bfloat16_as_ushort(l0) |
                                           ((uint32_t)__bfloat16_as_ushort(l1) << 16);
                }
            }
        }
    }
}

// ---------------- one-pass fp32 -> bf16 hi/lo decomposition (x + 4 weights) ----------------
#define DN0 (MROWS * DMODEL)
#define DN1 (2 * DIN * DMODEL)
#define DN2 (XPW * DIN)
#define DN3 (DIN * DTR)
#define DN4 (DMODEL * DIN)
#define DNT (DN0 + DN1 + DN2 + DN3 + DN4)

__global__ void __launch_bounds__(256)
decomp_all(const float* __restrict__ x,  const float* __restrict__ Wi,
           const float* __restrict__ Wx, const float* __restrict__ Wd,
           const float* __restrict__ Wo)
{
    int i = (blockIdx.x * 256 + threadIdx.x) * 4;
    if (i >= DNT) return;
    const float* s; bf16 *h, *l;
    if (i < DN0)                          { s = x  + i;                        h = g_xh  + i;  l = g_xl  + i; }
    else if (i < DN0 + DN1)               { int j = i - DN0;                   s = Wi + j; h = g_Wih + j; l = g_Wil + j; }
    else if (i < DN0 + DN1 + DN2)         { int j = i - DN0 - DN1;             s = Wx + j; h = g_Wxh + j; l = g_Wxl + j; }
    else if (i < DN0 + DN1 + DN2 + DN3)   { int j = i - DN0 - DN1 - DN2;       s = Wd + j; h = g_Wdh + j; l = g_Wdl + j; }
    else                                  { int j = i - DN0 - DN1 - DN2 - DN3; s = Wo + j; h = g_Woh + j; l = g_Wol + j; }
    float4 v = *(const float4*)s;
    bf16 h0, l0, h1, l1, h2, l2, h3, l3;
    decomp1(v.x, h0, l0); decomp1(v.y, h1, l1);
    decomp1(v.z, h2, l2); decomp1(v.w, h3, l3);
    *(uint2*)h = make_uint2(
        (uint32_t)__bfloat16_as_ushort(h0) | ((uint32_t)__bfloat16_as_ushort(h1) << 16),
        (uint32_t)__bfloat16_as_ushort(h2) | ((uint32_t)__bfloat16_as_ushort(h3) << 16));
    *(uint2*)l = make_uint2(
        (uint32_t)__bfloat16_as_ushort(l0) | ((uint32_t)__bfloat16_as_ushort(l1) << 16),
        (uint32_t)__bfloat16_as_ushort(l2) | ((uint32_t)__bfloat16_as_ushort(l3) << 16));
}

// ---------------- split-K reduce for x_proj (+ hi/lo of delta-lowrank cols) ----------------
__global__ void reduce_xp_kernel(const float* __restrict__ part, float* __restrict__ xp,
                                 bf16* __restrict__ xph, bf16* __restrict__ xpl)
{
    const int i = blockIdx.x * 256 + threadIdx.x;
    if (i >= MROWS * XPW) return;
    float s = 0.f;
#pragma unroll
    for (int k = 0; k < XSPLIT; k++) s += part[(size_t)k * MROWS * XPW + i];
    xp[i] = s;
    const int col = i % XPW;
    if (col < DTR) {
        const int row = i / XPW;
        bf16 h, l;
        decomp1(s, h, l);
        xph[row * DTR + col] = h;
        xpl[row * DTR + col] = l;
    }
}

// ---------------- split-K reduce for out_proj (+bias) ----------------
__global__ void reduce_out_kernel(const float* __restrict__ part,
                                  const float* __restrict__ bias,
                                  float* __restrict__ out)
{
    const int i = (blockIdx.x * 256 + threadIdx.x) * 4;
    if (i >= MROWS * DMODEL) return;
    float4 a = *(const float4*)(part + i);
    float4 b = *(const float4*)(part + (size_t)MROWS * DMODEL + i);
    float4 bb = *(const float4*)(bias + (i % DMODEL));
    float4 r;
    r.x = a.x + b.x + bb.x;
    r.y = a.y + b.y + bb.y;
    r.z = a.z + b.z + bb.z;
    r.w = a.w + b.w + bb.w;
    *(float4*)(out + i) = r;
}

// ---------------- depthwise causal conv1d (k=3) + SiLU -> bf16 hi/lo ----------------
__global__ void conv_silu_kernel(const float* __restrict__ xr,
                                 const float* __restrict__ conv_w,
                                 const float* __restrict__ conv_b,
                                 bf16* __restrict__ uh, bf16* __restrict__ ul)
{
    const int idx = blockIdx.x * blockDim.x + threadIdx.x;
    if (idx >= MROWS * DIN) return;
    const int d = idx % DIN;
    const int l = (idx / DIN) % LEN;
    const int b = idx / (DIN * LEN);

    const float* xc = xr + (size_t)b * LEN * (2 * DIN);
    const float w0 = conv_w[d * 3 + 0];
    const float w1 = conv_w[d * 3 + 1];
    const float w2 = conv_w[d * 3 + 2];

    float acc = conv_b[d];
    if (l >= 2) acc = fmaf(w0, xc[(size_t)(l - 2) * (2 * DIN) + d], acc);
    if (l >= 1) acc = fmaf(w1, xc[(size_t)(l - 1) * (2 * DIN) + d], acc);
    acc = fmaf(w2, xc[(size_t)l * (2 * DIN) + d], acc);
    const float v = acc / (1.f + __expf(-acc));
    bf16 h, lo;
    decomp1(v, h, lo);
    uh[idx] = h;
    ul[idx] = lo;
}

// ---------------- chunked selective scan + output gate -> bf16 hi/lo ----------------
__global__ void __launch_bounds__(256)
scan_kernel(const float* __restrict__ xp,
            const bf16* __restrict__ dlh, const bf16* __restrict__ dll,
            const bf16* __restrict__ uh,  const bf16* __restrict__ ul,
            const float* __restrict__ xr, const float* __restrict__ A_log,
            bf16* __restrict__ yh, bf16* __restrict__ yl)
{
    const int d = blockIdx.x * 256 + threadIdx.x;
    const int c = blockIdx.y;
    const int b = blockIdx.z;
    const int base_l = c * CHUNK;

    __shared__ float Bs[CHUNK][NST];
    __shared__ float Cs[CHUNK][NST];
    for (int i = threadIdx.x; i < CHUNK * NST; i += 256) {
        const int l = i / NST, n = i % NST;
        const float* row = xp + (size_t)(b * LEN + base_l + l) * XPW;
        Bs[l][n] = row[DTR + n];
        Cs[l][n] = row[DTR + NST + n];
    }
    __syncthreads();

    float aA[NST];
#pragma unroll
    for (int n = 0; n < NST; n++) aA[n] = -__expf(A_log[d * NST + n]);

    float s[NST];
#pragma unroll
    for (int n = 0; n < NST; n++) s[n] = 0.f;

    for (int l = 0; l < CHUNK; l++) {
        const size_t idx = (size_t)(b * LEN + base_l + l) * DIN + d;
        const float dl = __bfloat162float(dlh[idx]) + __bfloat162float(dll[idx]);
        const float uu = __bfloat162float(uh[idx]) + __bfloat162float(ul[idx]);
        const float du = dl * uu;
        float acc = 0.f;
#pragma unroll
        for (int n = 0; n < NST; n++) {
            const float dA = __expf(dl * aA[n]);
            s[n] = fmaf(dA, s[n], du * Bs[l][n]);
            acc  = fmaf(s[n], Cs[l][n], acc);
        }
        const float r  = xr[(size_t)(b * LEN + base_l + l) * (2 * DIN) + DIN + d];
        const float sr = r / (1.f + __expf(-r));
        const float yv = acc * sr;
        bf16 h, lo;
        decomp1(yv, h, lo);
        yh[idx] = h;
        yl[idx] = lo;
    }
}

// ---------------- launcher ----------------
extern "C" void kernel_launch(void* const* d_in, const int* in_sizes, int n_in,
                              void* d_out, int out_size)
{
    const float* x      = (const float*)d_in[0];
    const float* W_in   = (const float*)d_in[1];
    const float* b_in   = (const float*)d_in[2];
    const float* conv_w = (const float*)d_in[3];
    const float* conv_b = (const float*)d_in[4];
    const float* W_x    = (const float*)d_in[5];
    const float* W_dt   = (const float*)d_in[6];
    const float* b_dt   = (const float*)d_in[7];
    const float* A_log  = (const float*)d_in[8];
    const float* W_out  = (const float*)d_in[9];
    const float* b_out  = (const float*)d_in[10];
    float* out = (float*)d_out;

    float *xr, *xp, *xpp, *op;
    bf16 *xh, *xl, *uh, *ul, *xph, *xpl, *dlh, *dll, *yh, *yl;
    bf16 *Wih, *Wil, *Wxh, *Wxl, *Wdh, *Wdl, *Woh, *Wol;
    cudaGetSymbolAddress((void**)&xr,  g_xr);
    cudaGetSymbolAddress((void**)&xp,  g_xp);
    cudaGetSymbolAddress((void**)&xpp, g_xpp);
    cudaGetSymbolAddress((void**)&op,  g_op);
    cudaGetSymbolAddress((void**)&xh,  g_xh);
    cudaGetSymbolAddress((void**)&xl,  g_xl);
    cudaGetSymbolAddress((void**)&uh,  g_uh);
    cudaGetSymbolAddress((void**)&ul,  g_ul);
    cudaGetSymbolAddress((void**)&xph, g_xph);
    cudaGetSymbolAddress((void**)&xpl, g_xpl);
    cudaGetSymbolAddress((void**)&dlh, g_dlh);
    cudaGetSymbolAddress((void**)&dll, g_dll);
    cudaGetSymbolAddress((void**)&yh,  g_yh);
    cudaGetSymbolAddress((void**)&yl,  g_yl);
    cudaGetSymbolAddress((void**)&Wih, g_Wih);
    cudaGetSymbolAddress((void**)&Wil, g_Wil);
    cudaGetSymbolAddress((void**)&Wxh, g_Wxh);
    cudaGetSymbolAddress((void**)&Wxl, g_Wxl);
    cudaGetSymbolAddress((void**)&Wdh, g_Wdh);
    cudaGetSymbolAddress((void**)&Wdl, g_Wdl);
    cudaGetSymbolAddress((void**)&Woh, g_Woh);
    cudaGetSymbolAddress((void**)&Wol, g_Wol);

    cudaFuncSetAttribute(gemm_bf<0>, cudaFuncAttributeMaxDynamicSharedMemorySize, GSMEM);
    cudaFuncSetAttribute(gemm_bf<1>, cudaFuncAttributeMaxDynamicSharedMemorySize, GSMEM);

    // 0) decompose x + all weights -> bf16 hi/lo
    decomp_all<<<(DNT / 4 + 255) / 256, 256>>>(x, W_in, W_x, W_dt, W_out);

    // 1) in_proj: xr[2048,4096] = x @ W_in^T + b_in  (fp32 out)  [256 CTAs]
    gemm_bf<0><<<dim3(2 * DIN / 128, MROWS / 128, 1), 256, GSMEM>>>(
        xh, xl, Wih, Wil, b_in, xr, nullptr, nullptr,
        MROWS, 2 * DIN, DMODEL, DMODEL, DMODEL, 2 * DIN);

    // 2) depthwise causal conv + silu -> uh/ul
    conv_silu_kernel<<<(MROWS * DIN + 255) / 256, 256>>>(xr, conv_w, conv_b, uh, ul);

    // 3) x_proj split-K partials (16 slices of K=128)  [256 CTAs]
    gemm_bf<0><<<dim3(1, MROWS / 128, XSPLIT), 256, GSMEM>>>(
        uh, ul, Wxh, Wxl, nullptr, xpp, nullptr, nullptr,
        MROWS, XPW, DIN / XSPLIT, DIN, DIN, XPW);

    // 3b) reduce partials -> xp (+ hi/lo of dlt cols)
    reduce_xp_kernel<<<(MROWS * XPW + 255) / 256, 256>>>(xpp, xp, xph, xpl);

    // 4) delta = softplus( dlt @ W_dt^T + b_dt ) -> bf16 hi/lo  [256 CTAs]
    gemm_bf<1><<<dim3(DIN / 128, MROWS / 128, 1), 256, GSMEM>>>(
        xph, xpl, Wdh, Wdl, b_dt, nullptr, dlh, dll,
        MROWS, DIN, DTR, DTR, DTR, DIN);

    // 5) chunked scan + gate -> yh/yl
    scan_kernel<<<dim3(DIN / 256, NC, BSZ), 256>>>(xp, dlh, dll, uh, ul, xr, A_log, yh, yl);

    // 6) out_proj split-K=2 partials  [256 CTAs]
    gemm_bf<0><<<dim3(DMODEL / 128, MROWS / 128, OSPLIT), 256, GSMEM>>>(
        yh, yl, Woh, Wol, nullptr, op, nullptr, nullptr,
        MROWS, DMODEL, DIN / OSPLIT, DIN, DIN, DMODEL);

    // 6b) reduce partials + bias -> out
    reduce_out_kernel<<<(MROWS * DMODEL / 4 + 255) / 256, 256>>>(op, b_out, out);
}